// round 2
// baseline (speedup 1.0000x reference)
#include <cuda_runtime.h>
#include <cstdint>

// VoxelUnshuffle (strided pairing): out[n, c*VOLUME + i] = features[n*VOLUME + i, c]
// VOLUME = 8, C = 32  ->  per-voxel 8x32 transpose.
//
// Thread = one output float4 (16B). For output row n, float4 index j (0..63):
//   c = j >> 1, i_base = (j & 1) * 4
//   v.{x,y,z,w} = features[n*8 + i_base + k, c]  (k = 0..3)
// Writes: fully coalesced float4.
// Reads: per warp, each of the 4 scalar loads covers contiguous 16-float runs
// spanning whole 128B lines -> every fetched sector fully consumed.

__global__ void __launch_bounds__(256)
voxel_unshuffle_kernel(const float* __restrict__ in, float4* __restrict__ out,
                       long long n_out4)
{
    long long idx = (long long)blockIdx.x * blockDim.x + threadIdx.x;
    if (idx >= n_out4) return;

    long long n = idx >> 6;          // 64 float4 per output row (256 floats)
    int j       = (int)(idx & 63);
    int c       = j >> 1;
    int ib      = (j & 1) << 2;      // 0 or 4

    const float* base = in + n * 256 + (long long)ib * 32 + c;

    float4 v;
    v.x = __ldg(base + 0 * 32);
    v.y = __ldg(base + 1 * 32);
    v.z = __ldg(base + 2 * 32);
    v.w = __ldg(base + 3 * 32);

    out[idx] = v;
}

// Indices passthrough: harness output dtype is float32, so the reference's
// int32 indices are compared as float VALUES. Convert int -> float.
__global__ void __launch_bounds__(256)
i32_to_f32_kernel(const int4* __restrict__ src, float4* __restrict__ dst,
                  long long n4)
{
    long long idx = (long long)blockIdx.x * blockDim.x + threadIdx.x;
    if (idx >= n4) return;
    int4 s = src[idx];
    float4 d;
    d.x = (float)s.x;
    d.y = (float)s.y;
    d.z = (float)s.z;
    d.w = (float)s.w;
    dst[idx] = d;
}

extern "C" void kernel_launch(void* const* d_in, const int* in_sizes, int n_in,
                              void* d_out, int out_size)
{
    const float* features = (const float*)d_in[0];
    long long feat_elems  = (long long)in_sizes[0];      // 4,000,000 * 32
    long long n_out4      = feat_elems >> 2;             // float4 count

    {
        int threads = 256;
        long long blocks = (n_out4 + threads - 1) / threads;
        voxel_unshuffle_kernel<<<(unsigned)blocks, threads>>>(
            features, (float4*)d_out, n_out4);
    }

    // Second output (indices passthrough) packed after the features output.
    if (n_in >= 2 && (long long)out_size > feat_elems) {
        long long tail = (long long)out_size - feat_elems;
        long long idx_elems = (long long)in_sizes[1];    // 500,000 * 4 (div by 4)
        long long n_copy = tail < idx_elems ? tail : idx_elems;
        long long n4 = n_copy >> 2;                      // 2,000,000 -> 500,000 int4
        int threads = 256;
        long long blocks = (n4 + threads - 1) / threads;
        i32_to_f32_kernel<<<(unsigned)blocks, threads>>>(
            (const int4*)d_in[1], (float4*)d_out + (feat_elems >> 2), n4);
        // Handle any non-multiple-of-4 remainder (not expected here: 2,000,000 % 4 == 0)
    }
}

// round 3
// speedup vs baseline: 1.0027x; 1.0027x over previous
#include <cuda_runtime.h>
#include <cstdint>

// VoxelUnshuffle (strided pairing): out[n, c*8 + i] = features[n*8 + i, c]
// Fused single kernel:
//   blocks [0, featBlocks)  : per-voxel 8x32 transpose, one thread = one output float4
//   blocks [featBlocks, ..) : indices passthrough int32 -> float32 (harness output is f32)

__global__ void __launch_bounds__(256)
voxel_unshuffle_fused(const float* __restrict__ in, float4* __restrict__ out,
                      long long n_out4,
                      const int4* __restrict__ idx_src, float4* __restrict__ idx_dst,
                      long long n_idx4, long long feat_threads)
{
    long long t = (long long)blockIdx.x * blockDim.x + threadIdx.x;

    if (t < feat_threads) {
        if (t >= n_out4) return;
        long long n = t >> 6;            // 64 float4 per output row (256 floats)
        int j       = (int)(t & 63);
        int c       = j >> 1;
        int ib      = (j & 1) << 2;      // 0 or 4

        const float* base = in + n * 256 + (long long)ib * 32 + c;

        float4 v;
        asm volatile("ld.global.cs.f32 %0, [%1];"      : "=f"(v.x) : "l"(base));
        asm volatile("ld.global.cs.f32 %0, [%1+128];"  : "=f"(v.y) : "l"(base));
        asm volatile("ld.global.cs.f32 %0, [%1+256];"  : "=f"(v.z) : "l"(base));
        asm volatile("ld.global.cs.f32 %0, [%1+384];"  : "=f"(v.w) : "l"(base));

        asm volatile("st.global.cs.v4.f32 [%0], {%1,%2,%3,%4};"
                     :: "l"(out + t), "f"(v.x), "f"(v.y), "f"(v.z), "f"(v.w));
    } else {
        long long k = t - feat_threads;
        if (k >= n_idx4) return;
        int4 s = idx_src[k];
        float4 d;
        d.x = (float)s.x; d.y = (float)s.y; d.z = (float)s.z; d.w = (float)s.w;
        idx_dst[k] = d;
    }
}

extern "C" void kernel_launch(void* const* d_in, const int* in_sizes, int n_in,
                              void* d_out, int out_size)
{
    const float* features = (const float*)d_in[0];
    long long feat_elems  = (long long)in_sizes[0];      // 4,000,000 * 32
    long long n_out4      = feat_elems >> 2;             // output float4 count

    long long n_idx4 = 0;
    const int4* idx_src = nullptr;
    float4* idx_dst = nullptr;
    if (n_in >= 2 && (long long)out_size > feat_elems) {
        long long tail      = (long long)out_size - feat_elems;
        long long idx_elems = (long long)in_sizes[1];
        long long n_copy    = tail < idx_elems ? tail : idx_elems;
        n_idx4  = n_copy >> 2;
        idx_src = (const int4*)d_in[1];
        idx_dst = (float4*)d_out + (feat_elems >> 2);
    }

    const int threads = 256;
    long long feat_blocks  = (n_out4 + threads - 1) / threads;
    long long feat_threads = feat_blocks * threads;       // round feature range to block
    long long idx_blocks   = (n_idx4 + threads - 1) / threads;
    long long blocks       = feat_blocks + idx_blocks;

    voxel_unshuffle_fused<<<(unsigned)blocks, threads>>>(
        features, (float4*)d_out, n_out4,
        idx_src, idx_dst, n_idx4, feat_threads);
}

// round 4
// speedup vs baseline: 1.0298x; 1.0270x over previous
#include <cuda_runtime.h>
#include <cstdint>

// VoxelUnshuffle (strided): out[n, c*8 + i] = features[n*8 + i, c]  (8x32 transpose per voxel)
//
// Warp-per-voxel layout: global thread g -> n = g>>5, j0 = g&31.
// Each thread produces output float4 j0 and j0+32 of voxel n:
//   c = j0>>1, ib = (j0&1)*4;  second half uses c+16, same ib.
// Per thread: 8 independent scalar loads (MLP=8), 2 float4 stores.
// Per warp: reads the voxel's 8 rows (8 x 128B lines, fully consumed),
//           writes two contiguous 512B bursts. No cross-warp sharing.

__global__ void __launch_bounds__(256)
voxel_unshuffle_fused(const float* __restrict__ in, float4* __restrict__ out,
                      long long feat_threads,    // n_voxels * 32 (rounded range below)
                      long long n_threads_feat,  // exact n_voxels * 32
                      const int4* __restrict__ idx_src, float4* __restrict__ idx_dst,
                      long long n_idx4)
{
    long long g = (long long)blockIdx.x * blockDim.x + threadIdx.x;

    if (g < feat_threads) {
        if (g >= n_threads_feat) return;
        long long n = g >> 5;
        int j0      = (int)(g & 31);
        int c       = j0 >> 1;
        int ib      = (j0 & 1) << 2;     // 0 or 4

        const float* base = in + n * 256 + (long long)ib * 32 + c;

        float4 a, b;
        a.x = __ldg(base +   0);
        a.y = __ldg(base +  32);
        a.z = __ldg(base +  64);
        a.w = __ldg(base +  96);
        b.x = __ldg(base +  16);
        b.y = __ldg(base +  48);
        b.z = __ldg(base +  80);
        b.w = __ldg(base + 112);

        float4* o = out + n * 64 + j0;
        asm volatile("st.global.cs.v4.f32 [%0], {%1,%2,%3,%4};"
                     :: "l"(o), "f"(a.x), "f"(a.y), "f"(a.z), "f"(a.w));
        asm volatile("st.global.cs.v4.f32 [%0], {%1,%2,%3,%4};"
                     :: "l"(o + 32), "f"(b.x), "f"(b.y), "f"(b.z), "f"(b.w));
    } else {
        long long k = g - feat_threads;
        if (k >= n_idx4) return;
        int4 s = idx_src[k];
        float4 d;
        d.x = (float)s.x; d.y = (float)s.y; d.z = (float)s.z; d.w = (float)s.w;
        idx_dst[k] = d;
    }
}

extern "C" void kernel_launch(void* const* d_in, const int* in_sizes, int n_in,
                              void* d_out, int out_size)
{
    const float* features = (const float*)d_in[0];
    long long feat_elems  = (long long)in_sizes[0];      // 4,000,000 * 32
    long long n_vox       = feat_elems >> 8;             // 256 floats per voxel
    long long n_feat_thr  = n_vox * 32;                  // one warp per voxel

    long long n_idx4 = 0;
    const int4* idx_src = nullptr;
    float4* idx_dst = nullptr;
    if (n_in >= 2 && (long long)out_size > feat_elems) {
        long long tail      = (long long)out_size - feat_elems;
        long long idx_elems = (long long)in_sizes[1];
        long long n_copy    = tail < idx_elems ? tail : idx_elems;
        n_idx4  = n_copy >> 2;
        idx_src = (const int4*)d_in[1];
        idx_dst = (float4*)d_out + (feat_elems >> 2);
    }

    const int threads = 256;
    long long feat_blocks  = (n_feat_thr + threads - 1) / threads;
    long long feat_threads = feat_blocks * threads;
    long long idx_blocks   = (n_idx4 + threads - 1) / threads;
    long long blocks       = feat_blocks + idx_blocks;

    voxel_unshuffle_fused<<<(unsigned)blocks, threads>>>(
        features, (float4*)d_out, feat_threads, n_feat_thr,
        idx_src, idx_dst, n_idx4);
}